// round 4
// baseline (speedup 1.0000x reference)
#include <cuda_runtime.h>
#include <cuda_bf16.h>

// Problem constants: T=1024, C_in=4, C_out=2, H=32
#define T_LEN 1024
#define C_IN  4
#define C_OUT 2
#define H_DIM 32

// Collapsed Toeplitz kernel K[d][o][c]  (32 KB)
__device__ float g_K[T_LEN * C_OUT * C_IN];

// ---------------------------------------------------------------------------
// Kernel 1: K[d,oc] = b2 + sum_h [A_och*sin(a_h*dt_d) + B_och*cos(a_h*dt_d)]
// with A = w2*cos(p), B = w2*sin(p), p = o*w1[h,2] + c*w1[h,1] + b1[h].
// 32 CTAs x 256 threads; CTA covers 32 d-values. Base sincos shared over the
// 8 (o,c) threads per d via smem -> 5 sincos per thread.
// ---------------------------------------------------------------------------
__global__ void __launch_bounds__(256)
ck_build_kernel(const float* __restrict__ t,
                const float* __restrict__ w1,   // [H,3] row-major
                const float* __restrict__ b1,   // [H]
                const float* __restrict__ w2,   // [H]
                const float* __restrict__ b2)   // [1]
{
    __shared__ float2 AB[H_DIM][8];     // (w2*cos p, w2*sin p) per (h, oc)
    __shared__ float2 sB[32][H_DIM + 1];// (sin, cos)(a_h * dt_d), padded
    const int tid = threadIdx.x;

    // Phase table: 256 entries, one per thread.
    {
        int h  = tid >> 3;
        int oc = tid & 7;
        float fo = (float)(oc >> 2);
        float fc = (float)(oc & 3);
        float p = fmaf(fo, __ldg(&w1[3 * h + 2]),
                   fmaf(fc, __ldg(&w1[3 * h + 1]), __ldg(&b1[h])));
        float sp, cp;
        __sincosf(p, &sp, &cp);
        float w = __ldg(&w2[h]);
        AB[h][oc] = make_float2(w * cp, w * sp);
    }

    // Base table: 32 d x 32 h = 1024 sincos, 4 per thread.
    const float t0 = t[0];
#pragma unroll
    for (int k = 0; k < 4; ++k) {
        int e  = tid + k * 256;
        int dl = e >> 5;               // local d
        int h  = e & 31;
        float dt = t0 - t[blockIdx.x * 32 + dl];
        float sb, cb;
        __sincosf(dt * __ldg(&w1[3 * h]), &sb, &cb);
        sB[dl][h] = make_float2(sb, cb);
    }
    __syncthreads();

    // Main: thread = (d_local, oc)
    const int dl = tid >> 3;
    const int oc = tid & 7;
    float acc = b2[0];
#pragma unroll
    for (int h = 0; h < H_DIM; ++h) {
        float2 bc = sB[dl][h];
        float2 ab = AB[h][oc];
        acc = fmaf(ab.x, bc.x, fmaf(ab.y, bc.y, acc));
    }
    g_K[(blockIdx.x * 32 + dl) * 8 + oc] = acc;
}

// ---------------------------------------------------------------------------
// Kernel 2: causal conv  y[i,o] = sum_{d<=i} sum_c K[d,o,c] * x[i-d, c]
// 256 CTAs x 256 threads; CTA owns 4 rows [4b, 4b+3]. Stages x[0..rmax] and
// K[0..rmax] into smem (coalesced), then 8 warps split d into 128-chunks.
// Lane = (d_sub in 8, r_sub in 4): per 8-d step, 3 LDS.128 + 8 FFMA.
// Butterfly-reduce over d_sub, combine warps via smem. Deterministic.
// ---------------------------------------------------------------------------
__global__ void __launch_bounds__(256)
ck_conv_kernel(const float* __restrict__ x,   // [T, C_IN] row-major
               float* __restrict__ y)         // [T, C_OUT] row-major
{
    __shared__ float4 sX[T_LEN];          // 16 KB: x rows (float4 = 4 channels)
    __shared__ float4 sK[2 * T_LEN];      // 32 KB: K[d] = 2 float4 (o=0,1)

    const int tid  = threadIdx.x;
    const int r0   = blockIdx.x * 4;
    const int rmax = r0 + 3;
    const int n    = rmax + 1;            // number of rows / d values needed

    const float4* __restrict__ x4 = (const float4*)x;
    const float4* __restrict__ K4 = (const float4*)g_K;

    for (int i = tid; i < n; i += 256)     sX[i] = __ldg(&x4[i]);
    for (int i = tid; i < 2 * n; i += 256) sK[i] = __ldg(&K4[i]);
    __syncthreads();

    const int warp  = tid >> 5;
    const int lane  = tid & 31;
    const int d_sub = lane >> 2;          // 0..7
    const int r_sub = lane & 3;           // 0..3
    const int row   = r0 + r_sub;

    float a0 = 0.0f, a1 = 0.0f;
    const int dbeg = warp << 7;
    const int dend = min(dbeg + 127, rmax);

    for (int db = dbeg; db <= dend; db += 8) {
        int dr = db + d_sub;              // this lane's d (may overshoot)
        int d  = min(dr, rmax);           // clamp for safe smem indexing
        float4 k0 = sK[2 * d];
        float4 k1 = sK[2 * d + 1];
        bool v  = (dr <= row);
        int  xi = v ? (row - dr) : 0;
        float4 xv = sX[xi];
        if (v) {
            a0 = fmaf(k0.x, xv.x, fmaf(k0.y, xv.y, fmaf(k0.z, xv.z, fmaf(k0.w, xv.w, a0))));
            a1 = fmaf(k1.x, xv.x, fmaf(k1.y, xv.y, fmaf(k1.z, xv.z, fmaf(k1.w, xv.w, a1))));
        }
    }

    // Reduce over d_sub (lane bits [2:5)).
#pragma unroll
    for (int m = 16; m >= 4; m >>= 1) {
        a0 += __shfl_xor_sync(0xffffffffu, a0, m);
        a1 += __shfl_xor_sync(0xffffffffu, a1, m);
    }

    // Combine the 8 warps. Reuse sX storage (all smem reads are done).
    __syncthreads();
    float2* part = (float2*)sX;           // part[warp*4 + r_sub]
    if (lane < 4) part[warp * 4 + lane] = make_float2(a0, a1);
    __syncthreads();

    if (tid < 4) {
        float s0 = 0.0f, s1 = 0.0f;
#pragma unroll
        for (int w = 0; w < 8; ++w) {
            float2 p = part[w * 4 + tid];
            s0 += p.x; s1 += p.y;
        }
        ((float2*)y)[r0 + tid] = make_float2(s0, s1);
    }
}

// ---------------------------------------------------------------------------
// Inputs (metadata order): x[T*C_IN], t[T], w1[H*3], b1[H], w2[H], b2[1],
// out_channels (unused — compile-time constant).
// ---------------------------------------------------------------------------
extern "C" void kernel_launch(void* const* d_in, const int* in_sizes, int n_in,
                              void* d_out, int out_size)
{
    const float* x  = (const float*)d_in[0];
    const float* t  = (const float*)d_in[1];
    const float* w1 = (const float*)d_in[2];
    const float* b1 = (const float*)d_in[3];
    const float* w2 = (const float*)d_in[4];
    const float* b2 = (const float*)d_in[5];
    float* y = (float*)d_out;

    ck_build_kernel<<<T_LEN / 32, 256>>>(t, w1, b1, w2, b2);
    ck_conv_kernel<<<T_LEN / 4, 256>>>(x, y);
}

// round 5
// speedup vs baseline: 1.2630x; 1.2630x over previous
#include <cuda_runtime.h>
#include <cuda_bf16.h>

// Problem constants: T=1024, C_in=4, C_out=2, H=32
#define T_LEN 1024
#define C_IN  4
#define C_OUT 2
#define H_DIM 32

// Collapsed Toeplitz kernel K[d][o][c]  (32 KB)
__device__ float g_K[T_LEN * C_OUT * C_IN];

// ---------------------------------------------------------------------------
// Kernel 1: K[d,oc] = b2 + sum_h [A_och*sin(a_h*dt_d) + B_och*cos(a_h*dt_d)]
// with A = w2*cos(p), B = w2*sin(p), p = o*w1[h,2] + c*w1[h,1] + b1[h].
// 64 CTAs x 128 threads; CTA covers 16 d-values. ~6 sincos + 64 FMA per thread.
// ---------------------------------------------------------------------------
__global__ void __launch_bounds__(128)
ck_build_kernel(const float* __restrict__ t,
                const float* __restrict__ w1,   // [H,3] row-major
                const float* __restrict__ b1,   // [H]
                const float* __restrict__ w2,   // [H]
                const float* __restrict__ b2)   // [1]
{
    __shared__ float2 AB[H_DIM][8];      // (w2*cos p, w2*sin p) per (h, oc)
    __shared__ float2 sB[16][H_DIM + 1]; // (sin, cos)(a_h * dt_d), padded
    const int tid = threadIdx.x;

    // Phase table: 256 entries, 2 per thread.
#pragma unroll
    for (int e = tid; e < H_DIM * 8; e += 128) {
        int h  = e >> 3;
        int oc = e & 7;
        float fo = (float)(oc >> 2);
        float fc = (float)(oc & 3);
        float p = fmaf(fo, __ldg(&w1[3 * h + 2]),
                   fmaf(fc, __ldg(&w1[3 * h + 1]), __ldg(&b1[h])));
        float sp, cp;
        __sincosf(p, &sp, &cp);
        float w = __ldg(&w2[h]);
        AB[h][oc] = make_float2(w * cp, w * sp);
    }

    // Base table: 16 d x 32 h = 512 sincos, 4 per thread.
    const float t0 = t[0];
#pragma unroll
    for (int k = 0; k < 4; ++k) {
        int e  = tid + k * 128;
        int dl = e >> 5;               // local d (0..15)
        int h  = e & 31;
        float dt = t0 - t[blockIdx.x * 16 + dl];
        float sb, cb;
        __sincosf(dt * __ldg(&w1[3 * h]), &sb, &cb);
        sB[dl][h] = make_float2(sb, cb);
    }
    __syncthreads();

    // Main: thread = (d_local in 16, oc in 8)
    const int dl = tid >> 3;
    const int oc = tid & 7;
    float acc = b2[0];
#pragma unroll
    for (int h = 0; h < H_DIM; ++h) {
        float2 bc = sB[dl][h];
        float2 ab = AB[h][oc];
        acc = fmaf(ab.x, bc.x, fmaf(ab.y, bc.y, acc));
    }
    g_K[(blockIdx.x * 16 + dl) * 8 + oc] = acc;
}

// ---------------------------------------------------------------------------
// Kernel 2: causal conv  y[i,o] = sum_{d<=i} sum_c K[d,o,c] * x[i-d, c]
// Row-pair decomposition: CTA a (128 threads) owns rows a and b=1023-a.
// Every pair has exactly 1025 d-terms -> perfectly uniform CTA work.
// No smem staging: direct coalesced LDG.128 from L2-resident K and x.
// Warp butterfly + 16-float smem combine. Deterministic.
// ---------------------------------------------------------------------------
__global__ void __launch_bounds__(128)
ck_conv_kernel(const float* __restrict__ x,   // [T, C_IN] row-major
               float* __restrict__ y)         // [T, C_OUT] row-major
{
    const int tid  = threadIdx.x;
    const int warp = tid >> 5;
    const int lane = tid & 31;
    const int a = blockIdx.x;        // 0..511 (small row)
    const int b = 1023 - a;          // large row (>= 512)

    const float4* __restrict__ x4 = (const float4*)x;     // one row per entry
    const float4* __restrict__ K4 = (const float4*)g_K;   // 2 float4 per d

    float a0 = 0.0f, a1 = 0.0f, b0 = 0.0f, b1 = 0.0f;

#pragma unroll 4
    for (int d = tid; d <= b; d += 128) {
        float4 k0 = __ldg(&K4[2 * d]);       // o=0, c=0..3
        float4 k1 = __ldg(&K4[2 * d + 1]);   // o=1, c=0..3
        float4 xb = __ldg(&x4[b - d]);
        b0 = fmaf(k0.x, xb.x, fmaf(k0.y, xb.y, fmaf(k0.z, xb.z, fmaf(k0.w, xb.w, b0))));
        b1 = fmaf(k1.x, xb.x, fmaf(k1.y, xb.y, fmaf(k1.z, xb.z, fmaf(k1.w, xb.w, b1))));
        if (d <= a) {
            float4 xa = __ldg(&x4[a - d]);
            a0 = fmaf(k0.x, xa.x, fmaf(k0.y, xa.y, fmaf(k0.z, xa.z, fmaf(k0.w, xa.w, a0))));
            a1 = fmaf(k1.x, xa.x, fmaf(k1.y, xa.y, fmaf(k1.z, xa.z, fmaf(k1.w, xa.w, a1))));
        }
    }

    // Warp butterfly reduction (four interleaved chains).
#pragma unroll
    for (int off = 16; off > 0; off >>= 1) {
        a0 += __shfl_xor_sync(0xffffffffu, a0, off);
        a1 += __shfl_xor_sync(0xffffffffu, a1, off);
        b0 += __shfl_xor_sync(0xffffffffu, b0, off);
        b1 += __shfl_xor_sync(0xffffffffu, b1, off);
    }

    __shared__ float4 part[4];
    if (lane == 0) part[warp] = make_float4(a0, a1, b0, b1);
    __syncthreads();

    if (tid == 0) {
        float4 p0 = part[0], p1 = part[1], p2 = part[2], p3 = part[3];
        float sx = (p0.x + p1.x) + (p2.x + p3.x);
        float sy = (p0.y + p1.y) + (p2.y + p3.y);
        float sz = (p0.z + p1.z) + (p2.z + p3.z);
        float sw = (p0.w + p1.w) + (p2.w + p3.w);
        ((float2*)y)[a] = make_float2(sx, sy);
        ((float2*)y)[b] = make_float2(sz, sw);
    }
}

// ---------------------------------------------------------------------------
// Inputs (metadata order): x[T*C_IN], t[T], w1[H*3], b1[H], w2[H], b2[1],
// out_channels (unused — compile-time constant).
// ---------------------------------------------------------------------------
extern "C" void kernel_launch(void* const* d_in, const int* in_sizes, int n_in,
                              void* d_out, int out_size)
{
    const float* x  = (const float*)d_in[0];
    const float* t  = (const float*)d_in[1];
    const float* w1 = (const float*)d_in[2];
    const float* b1 = (const float*)d_in[3];
    const float* w2 = (const float*)d_in[4];
    const float* b2 = (const float*)d_in[5];
    float* y = (float*)d_out;

    ck_build_kernel<<<T_LEN / 16, 128>>>(t, w1, b1, w2, b2);
    ck_conv_kernel<<<T_LEN / 2, 128>>>(x, y);
}